// round 5
// baseline (speedup 1.0000x reference)
#include <cuda_runtime.h>
#include <cuda_bf16.h>
#include <math.h>
#include <stdint.h>

#define NN 50000
#define EMAX 500000

// ---------------- scratch (device globals; no allocations allowed) ----------
// Split per-node features. A = dst-side, B = src-side. Stride 8*O bytes:
//   [0   ,2O ) q  bf16[O]
//   [2O  ,4O ) k  bf16[O]
//   [4O  ,8O ) v  f32 [O]
__device__ __align__(16) unsigned char g_featA[NN * 1024];
__device__ __align__(16) unsigned char g_featB[NN * 1024];
__device__ float g_x0[NN * 128];      // relu(layer0 out) f32 (residual + L1 GEMM input)
__device__ float g_h1[NN * 64];       // relu(layer1 out) f32 (L2 GEMM input)
__device__ float g_wcatT[768 * 128];  // transposed transformed weights [M][K], tf32
__device__ float g_bcat[768];         // concatenated bias (bias only on A columns)
// counting-sort scratch
__device__ int g_hist[NN];
__device__ int g_binoff[NN + 1];
__device__ int g_cursor[NN];
__device__ int g_ssrc[EMAX];

__device__ __forceinline__ float rna_tf32(float v) {
    float o;
    asm("cvt.rna.tf32.f32 %0, %1;" : "=f"(o) : "f"(v));
    return o;
}
__device__ __forceinline__ float ex2f(float v) {
    float o;
    asm("ex2.approx.f32 %0, %1;" : "=f"(o) : "f"(v));
    return o;
}

// ---------------- build W_catT[col][c] = rna([Wtop-Wbot | Wbot]); zero hist --
__global__ void build_wcat(const float* __restrict__ wq, const float* __restrict__ wk,
                           const float* __restrict__ wv, const float* __restrict__ bq,
                           const float* __restrict__ bk, const float* __restrict__ bv,
                           int C, int O) {
    int M = 6 * O;
    int idx = blockIdx.x * blockDim.x + threadIdx.x;
    if (idx < C * M) {
        int c = idx / M, col = idx % M;
        int grp = col / O, j = col % O;
        const float* w = (grp < 2) ? wq : (grp < 4 ? wk : wv);
        float top = w[c * O + j];
        float bot = w[(C + c) * O + j];
        float val = (grp & 1) ? bot : (top - bot);
        g_wcatT[(size_t)col * C + c] = rna_tf32(val);
    }
    if (idx < M) {
        int grp = idx / O, j = idx % O;
        const float* b = (grp < 2) ? bq : (grp < 4 ? bk : bv);
        g_bcat[idx] = (grp & 1) ? 0.0f : b[j];
    }
    if (idx < NN) g_hist[idx] = 0;  // prepare histogram for this layer's sort
}

// ---------------- counting sort: hist -> scan -> scatter ---------------------
__global__ void hist_kernel(const int* __restrict__ edst, int E) {
    int i = blockIdx.x * blockDim.x + threadIdx.x;
    if (i < E) atomicAdd(&g_hist[edst[i]], 1);
}

__global__ void scan_kernel() {
    __shared__ int sh[1024];
    int t = threadIdx.x;
    const int chunk = (NN + 1023) / 1024;  // 49
    int beg = t * chunk;
    int end = min(beg + chunk, NN);
    int s = 0;
    for (int i = beg; i < end; i++) s += g_hist[i];
    sh[t] = s;
    __syncthreads();
    for (int off = 1; off < 1024; off <<= 1) {
        int v = (t >= off) ? sh[t - off] : 0;
        __syncthreads();
        if (t >= off) sh[t] += v;
        __syncthreads();
    }
    int run = (t == 0) ? 0 : sh[t - 1];
    for (int i = beg; i < end; i++) {
        int h = g_hist[i];
        g_binoff[i] = run;
        g_cursor[i] = run;
        run += h;
    }
    if (t == 1023) g_binoff[NN] = run;
}

__global__ void scatter_kernel(const int* __restrict__ esrc,
                               const int* __restrict__ edst, int E) {
    int i = blockIdx.x * blockDim.x + threadIdx.x;
    if (i < E) {
        int d = edst[i];
        int pos = atomicAdd(&g_cursor[d], 1);
        g_ssrc[pos] = esrc[i];
    }
}

// ---------------- tf32 tensor-core GEMM --------------------------------------
// feat = A(NxK) @ g_wcatT^T + bias, written to split A/B node layout.
// srcsel: 0 -> Aext (layer-0 input x), 1 -> g_x0, 2 -> g_h1.
template <int K, int O>
__global__ __launch_bounds__(256, 2) void mma_gemm(const float* __restrict__ Aext,
                                                   int srcsel, int N) {
    const float* A = (srcsel == 0) ? Aext : ((srcsel == 1) ? g_x0 : g_h1);
    constexpr int PAD = 20;
    __shared__ float As[2][128 * PAD];
    __shared__ float Bs[2][128 * PAD];

    const int tid = threadIdx.x;
    const int lane = tid & 31;
    const int wid = tid >> 5;
    const int wm = (wid & 1) * 64;
    const int wn = (wid >> 1) * 32;
    const int bm = blockIdx.y * 128;
    const int bn = blockIdx.x * 128;

    float acc[4][4][4];
#pragma unroll
    for (int a = 0; a < 4; a++)
#pragma unroll
        for (int b = 0; b < 4; b++)
#pragma unroll
            for (int c = 0; c < 4; c++) acc[a][b][c] = 0.0f;

    const int r_ld = tid >> 1;
    const int ch0 = (tid & 1) * 2;
    const int garow = bm + r_ld;
    const float* aptr = A + (size_t)(garow < N ? garow : 0) * K;
    const int asz = (garow < N) ? 16 : 0;
    const float* bptr = g_wcatT + (size_t)(bn + r_ld) * K;

#define SMADDR(p) ((uint32_t)__cvta_generic_to_shared(p))

#define LOAD_STAGE(buf, k0)                                                          \
    {                                                                                \
        _Pragma("unroll") for (int i = 0; i < 2; i++) {                              \
            int ch = ch0 + i;                                                        \
            asm volatile("cp.async.cg.shared.global [%0], [%1], 16, %2;" ::"r"(      \
                             SMADDR(&As[buf][r_ld * PAD + ch * 4])),                 \
                         "l"(aptr + (k0) + ch * 4), "r"(asz));                       \
            asm volatile("cp.async.cg.shared.global [%0], [%1], 16;" ::"r"(          \
                             SMADDR(&Bs[buf][r_ld * PAD + ch * 4])),                 \
                         "l"(bptr + (k0) + ch * 4));                                 \
        }                                                                            \
        asm volatile("cp.async.commit_group;");                                      \
    }

    LOAD_STAGE(0, 0);
    constexpr int NIT = K / 16;
#pragma unroll
    for (int it = 0; it < NIT; it++) {
        const int buf = it & 1;
        if (it + 1 < NIT) {
            LOAD_STAGE(buf ^ 1, (it + 1) * 16);
            asm volatile("cp.async.wait_group 1;");
        } else {
            asm volatile("cp.async.wait_group 0;");
        }
        __syncthreads();

#pragma unroll
        for (int ks = 0; ks < 16; ks += 8) {
            uint32_t af[4][4];
#pragma unroll
            for (int mt = 0; mt < 4; mt++) {
                const float* p = &As[buf][(wm + mt * 16 + (lane & 15)) * PAD + ks +
                                          (lane >> 4) * 4];
                asm volatile(
                    "ldmatrix.sync.aligned.m8n8.x4.shared.b16 {%0,%1,%2,%3}, [%4];"
                    : "=r"(af[mt][0]), "=r"(af[mt][1]), "=r"(af[mt][2]), "=r"(af[mt][3])
                    : "r"(SMADDR(p)));
#pragma unroll
                for (int r = 0; r < 4; r++)
                    af[mt][r] = __float_as_uint(rna_tf32(__uint_as_float(af[mt][r])));
            }
            uint32_t bf[2][4];
#pragma unroll
            for (int bi = 0; bi < 2; bi++) {
                const float* p = &Bs[buf][(wn + bi * 16 + (lane & 7) +
                                           ((lane >> 4) << 3)) *
                                              PAD +
                                          ks + ((lane >> 3) & 1) * 4];
                asm volatile(
                    "ldmatrix.sync.aligned.m8n8.x4.shared.b16 {%0,%1,%2,%3}, [%4];"
                    : "=r"(bf[bi][0]), "=r"(bf[bi][1]), "=r"(bf[bi][2]), "=r"(bf[bi][3])
                    : "r"(SMADDR(p)));
            }
#pragma unroll
            for (int mt = 0; mt < 4; mt++)
#pragma unroll
                for (int nt = 0; nt < 4; nt++) {
                    uint32_t b0 = bf[nt >> 1][(nt & 1) * 2];
                    uint32_t b1 = bf[nt >> 1][(nt & 1) * 2 + 1];
                    asm volatile(
                        "mma.sync.aligned.m16n8k8.row.col.f32.tf32.tf32.f32 "
                        "{%0,%1,%2,%3}, {%4,%5,%6,%7}, {%8,%9}, {%0,%1,%2,%3};"
                        : "+f"(acc[mt][nt][0]), "+f"(acc[mt][nt][1]),
                          "+f"(acc[mt][nt][2]), "+f"(acc[mt][nt][3])
                        : "r"(af[mt][0]), "r"(af[mt][1]), "r"(af[mt][2]),
                          "r"(af[mt][3]), "r"(b0), "r"(b1));
                }
        }
        __syncthreads();
    }

    // Epilogue: add bias, write split A/B mixed-precision layout.
#pragma unroll
    for (int mt = 0; mt < 4; mt++) {
        int r = bm + wm + mt * 16 + (lane >> 2);
#pragma unroll
        for (int half = 0; half < 2; half++) {
            int rr = r + half * 8;
            if (rr < N) {
                unsigned char* baseA = g_featA + (size_t)rr * (8 * O);
                unsigned char* baseB = g_featB + (size_t)rr * (8 * O);
#pragma unroll
                for (int nt = 0; nt < 4; nt++) {
                    int c = bn + wn + nt * 8 + (lane & 3) * 2;
                    int grp = c / O;
                    int j = c - grp * O;
                    float ox = acc[mt][nt][half * 2 + 0] + g_bcat[c];
                    float oy = acc[mt][nt][half * 2 + 1] + g_bcat[c + 1];
                    unsigned char* base = (grp & 1) ? baseB : baseA;
                    int reg = grp >> 1;  // 0=q, 1=k, 2=v
                    if (reg < 2) {
                        __nv_bfloat162 h2 = __floats2bfloat162_rn(ox, oy);
                        *(__nv_bfloat162*)(base + reg * (2 * O) + j * 2) = h2;
                    } else {
                        *(float2*)(base + 4 * O + j * 4) = make_float2(ox, oy);
                    }
                }
            }
        }
    }
#undef LOAD_STAGE
#undef SMADDR
}

// ---------------- node kernel: warp per dst node (fused aggregate+finalize) --
// mode 0: g_x0 = relu(mean); mode 1: g_h1 = relu(mean);
// mode 2: out = relu(mean + g_x0)
template <int O>
__global__ __launch_bounds__(256) void node_kernel(float* __restrict__ outp, int mode) {
    constexpr int CPT = O / 32;   // 4 or 2
    constexpr int NH2 = CPT / 2;  // bf16x2 regs: 2 or 1
    const float CEXP = ((O == 128) ? 0.25f : 0.3535533905932738f) * 1.44269504f;

    int d = (blockIdx.x * blockDim.x + threadIdx.x) >> 5;
    int lane = threadIdx.x & 31;
    if (d >= NN) return;

    int beg = g_binoff[d];
    int end = g_binoff[d + 1];
    const unsigned char* fa = g_featA + (size_t)d * (8 * O);
    int c = lane * CPT;

    __nv_bfloat162 qa2[NH2], ka2[NH2];
    float va[CPT], acc[CPT];
    if constexpr (NH2 == 2) {
        uint2 uq = __ldg((const uint2*)(fa + c * 2));
        uint2 uk = __ldg((const uint2*)(fa + 2 * O + c * 2));
        qa2[0] = *(__nv_bfloat162*)&uq.x;
        qa2[1] = *(__nv_bfloat162*)&uq.y;
        ka2[0] = *(__nv_bfloat162*)&uk.x;
        ka2[1] = *(__nv_bfloat162*)&uk.y;
        float4 v4 = __ldg((const float4*)(fa + 4 * O + c * 4));
        va[0] = v4.x; va[1] = v4.y; va[2] = v4.z; va[3] = v4.w;
    } else {
        uint32_t uq = __ldg((const uint32_t*)(fa + c * 2));
        uint32_t uk = __ldg((const uint32_t*)(fa + 2 * O + c * 2));
        qa2[0] = *(__nv_bfloat162*)&uq;
        ka2[0] = *(__nv_bfloat162*)&uk;
        float2 v2 = __ldg((const float2*)(fa + 4 * O + c * 4));
        va[0] = v2.x; va[1] = v2.y;
    }
#pragma unroll
    for (int i = 0; i < CPT; i++) acc[i] = 0.0f;

    for (int j = beg; j < end; j++) {
        int s = __ldg(&g_ssrc[j]);
        const unsigned char* fb = g_featB + (size_t)s * (8 * O);
        __nv_bfloat162 qb2[NH2], kb2[NH2];
        float vb[CPT];
        if constexpr (NH2 == 2) {
            uint2 uq = __ldg((const uint2*)(fb + c * 2));
            uint2 uk = __ldg((const uint2*)(fb + 2 * O + c * 2));
            qb2[0] = *(__nv_bfloat162*)&uq.x;
            qb2[1] = *(__nv_bfloat162*)&uq.y;
            kb2[0] = *(__nv_bfloat162*)&uk.x;
            kb2[1] = *(__nv_bfloat162*)&uk.y;
            float4 v4 = __ldg((const float4*)(fb + 4 * O + c * 4));
            vb[0] = v4.x; vb[1] = v4.y; vb[2] = v4.z; vb[3] = v4.w;
        } else {
            uint32_t uq = __ldg((const uint32_t*)(fb + c * 2));
            uint32_t uk = __ldg((const uint32_t*)(fb + 2 * O + c * 2));
            qb2[0] = *(__nv_bfloat162*)&uq;
            kb2[0] = *(__nv_bfloat162*)&uk;
            float2 v2 = __ldg((const float2*)(fb + 4 * O + c * 4));
            vb[0] = v2.x; vb[1] = v2.y;
        }

        float z[CPT];
#pragma unroll
        for (int h = 0; h < NH2; h++) {
            __nv_bfloat162 t =
                __hmul2(__hadd2(qa2[h], qb2[h]), __hadd2(ka2[h], kb2[h]));
            float2 f = __bfloat1622float2(t);
            z[2 * h] = f.x;
            z[2 * h + 1] = f.y;
        }
        float m = z[0];
#pragma unroll
        for (int i = 1; i < CPT; i++) m = fmaxf(m, z[i]);
        m = fmaxf(m, __shfl_xor_sync(0xFFFFFFFFu, m, 1));
        m = fmaxf(m, __shfl_xor_sync(0xFFFFFFFFu, m, 2));

        float p[CPT], sum = 0.0f;
#pragma unroll
        for (int i = 0; i < CPT; i++) {
            p[i] = ex2f((z[i] - m) * CEXP);
            sum += p[i];
        }
        sum += __shfl_xor_sync(0xFFFFFFFFu, sum, 1);
        sum += __shfl_xor_sync(0xFFFFFFFFu, sum, 2);

        int dd = abs(d - s);
        float ew = (dd > 8) ? 1.0f : ((dd == 8) ? 0.0f : -1.0f);
        float w = ew / sum;
#pragma unroll
        for (int i = 0; i < CPT; i++)
            acc[i] = fmaf(p[i] * w, va[i] + vb[i], acc[i]);
    }

    float invdeg = 1.0f / (float)max(end - beg, 1);
    int idx0 = d * O + c;
    float vv[CPT];
#pragma unroll
    for (int i = 0; i < CPT; i++) vv[i] = acc[i] * invdeg;

    if (mode == 2) {
        if constexpr (CPT == 4) {
            float4 r = *(const float4*)(g_x0 + idx0);
            float4 o;
            o.x = fmaxf(vv[0] + r.x, 0.0f);
            o.y = fmaxf(vv[1] + r.y, 0.0f);
            o.z = fmaxf(vv[2] + r.z, 0.0f);
            o.w = fmaxf(vv[3] + r.w, 0.0f);
            *(float4*)(outp + idx0) = o;
        } else {
            float2 r = *(const float2*)(g_x0 + idx0);
            float2 o;
            o.x = fmaxf(vv[0] + r.x, 0.0f);
            o.y = fmaxf(vv[1] + r.y, 0.0f);
            *(float2*)(outp + idx0) = o;
        }
    } else {
        float* dst = (mode == 0) ? g_x0 : g_h1;
        if constexpr (CPT == 4) {
            float4 o;
            o.x = fmaxf(vv[0], 0.0f);
            o.y = fmaxf(vv[1], 0.0f);
            o.z = fmaxf(vv[2], 0.0f);
            o.w = fmaxf(vv[3], 0.0f);
            *(float4*)(dst + idx0) = o;
        } else {
            float2 o;
            o.x = fmaxf(vv[0], 0.0f);
            o.y = fmaxf(vv[1], 0.0f);
            *(float2*)(dst + idx0) = o;
        }
    }
}

// ---------------- launch -----------------------------------------------------
extern "C" void kernel_launch(void* const* d_in, const int* in_sizes, int n_in,
                              void* d_out, int out_size) {
    const float* x = (const float*)d_in[0];
    const int* e0 = (const int*)d_in[1];
    const int* e1 = (const int*)d_in[2];
    const int* e2 = (const int*)d_in[3];
    const float* wq0 = (const float*)d_in[5];
    const float* bq0 = (const float*)d_in[6];
    const float* wk0 = (const float*)d_in[7];
    const float* bk0 = (const float*)d_in[8];
    const float* wv0 = (const float*)d_in[9];
    const float* bv0 = (const float*)d_in[10];
    const float* wq1 = (const float*)d_in[11];
    const float* bq1 = (const float*)d_in[12];
    const float* wk1 = (const float*)d_in[13];
    const float* bk1 = (const float*)d_in[14];
    const float* wv1 = (const float*)d_in[15];
    const float* bv1 = (const float*)d_in[16];
    const float* wq2 = (const float*)d_in[17];
    const float* bq2 = (const float*)d_in[18];
    const float* wk2 = (const float*)d_in[19];
    const float* bk2 = (const float*)d_in[20];
    const float* wv2 = (const float*)d_in[21];
    const float* bv2 = (const float*)d_in[22];

    int E0 = in_sizes[1] / 2;
    int E1 = in_sizes[2] / 2;
    int E2 = in_sizes[3] / 2;

    int nblk = (NN + 127) / 128;
    int nodeGrid = (NN * 32 + 255) / 256;  // warp per node
    // build_wcat grid covers max(C*M, NN) threads
    int bw0 = (128 * 768 + 255) / 256;
    int bw1 = max((128 * 384 + 255) / 256, (NN + 255) / 256);
    int bw2 = max((64 * 768 + 255) / 256, (NN + 255) / 256);

    // ---- Layer 0: C=128, O=128 ----
    build_wcat<<<bw0, 256>>>(wq0, wk0, wv0, bq0, bk0, bv0, 128, 128);
    hist_kernel<<<(E0 + 255) / 256, 256>>>(e0 + E0, E0);
    scan_kernel<<<1, 1024>>>();
    scatter_kernel<<<(E0 + 255) / 256, 256>>>(e0, e0 + E0, E0);
    mma_gemm<128, 128><<<dim3(6, nblk), 256>>>(x, 0, NN);
    node_kernel<128><<<nodeGrid, 256>>>(nullptr, 0);

    // ---- Layer 1: C=128, O=64 ----
    build_wcat<<<bw1, 256>>>(wq1, wk1, wv1, bq1, bk1, bv1, 128, 64);
    hist_kernel<<<(E1 + 255) / 256, 256>>>(e1 + E1, E1);
    scan_kernel<<<1, 1024>>>();
    scatter_kernel<<<(E1 + 255) / 256, 256>>>(e1, e1 + E1, E1);
    mma_gemm<128, 64><<<dim3(3, nblk), 256>>>(nullptr, 1, NN);
    node_kernel<64><<<nodeGrid, 256>>>(nullptr, 1);

    // ---- Layer 2: C=64, O=128 ----
    build_wcat<<<bw2, 256>>>(wq2, wk2, wv2, bq2, bk2, bv2, 64, 128);
    hist_kernel<<<(E2 + 255) / 256, 256>>>(e2 + E2, E2);
    scan_kernel<<<1, 1024>>>();
    scatter_kernel<<<(E2 + 255) / 256, 256>>>(e2, e2 + E2, E2);
    mma_gemm<64, 128><<<dim3(6, nblk), 256>>>(nullptr, 2, NN);
    node_kernel<128><<<nodeGrid, 256>>>((float*)d_out, 2);
}